// round 14
// baseline (speedup 1.0000x reference)
#include <cuda_runtime.h>
#include <math.h>

#define NB    2
#define NPTS  8192
#define KNN   20
#define GDIM  16
#define G3    (GDIM*GDIM*GDIM)
#define CHUNK 32
#define NCH   (NPTS/CHUNK)    // 256
#define NSPL  4
#define KTHR  128
#define CBUF  16

// ---------------- device scratch (no allocation allowed) ----------------
__device__ int    g_knn[NB * NPTS * KNN];
__device__ float  g_S1[128], g_S2[128], g_SN[64];
__device__ float  g_base1[NB][128];
__device__ float  g_baseN[NB][64];
// sorted-point structures
__device__ float4 g_pts4[NB * NPTS];     // Morton-cell-sorted (x,y,z, 0.5*|p|^2)
__device__ int    g_ids [NB * NPTS];
__device__ float4 g_chlo[NB][NCH];
__device__ float4 g_chhi[NB][NCH];

__device__ __forceinline__ float gelu_f(float x) {
    float y = 0.7978845608028654f * (x + 0.044715f * x * x * x);
    float e = __expf(2.0f * y);
    float th = 1.0f - 2.0f / (e + 1.0f);
    return 0.5f * x * (1.0f + th);
}

__device__ __forceinline__ float gelu_fast(float x) {
    float y = 0.7978845608028654f * fmaf(0.044715f * x * x, x, x);
    float t;
    asm("tanh.approx.f32 %0, %1;" : "=f"(t) : "f"(y));
    return 0.5f * x * (1.0f + t);
}

__device__ __forceinline__ int cell_of(float v, float lo, float inv) {
    int i = (int)((v - lo) * inv);
    return i < 0 ? 0 : (i > GDIM - 1 ? GDIM - 1 : i);
}

// 4-bit-per-axis Morton interleave: compact chunks => tight bboxes
__device__ __forceinline__ int morton3(int x, int y, int z) {
    int m = 0;
#pragma unroll
    for (int i = 0; i < 4; i++) {
        m |= (((x >> i) & 1) << (3 * i + 2))
           | (((y >> i) & 1) << (3 * i + 1))
           | (((z >> i) & 1) << (3 * i));
    }
    return m;
}

// ---------------- fused builder: bbox + count + scan + scatter + chunk bboxes ----------------
// one 1024-thread block per batch; counts/scan live in smem.
__global__ __launch_bounds__(1024) void build_kernel(const float* __restrict__ z)
{
    __shared__ int   scnt[G3];          // 16 KB
    __shared__ int   ssum[1024];        // 4 KB
    __shared__ float swlo[32][3], swhi[32][3];
    __shared__ float slo3[3], sinv3[3];

    const unsigned FULL = 0xffffffffu;
    const int b    = blockIdx.x;
    const int tid  = threadIdx.x;
    const int warp = tid >> 5;
    const int lane = tid & 31;
    const float* zb = z + (size_t)b * NPTS * 7;

    // ---- bbox ----
    float lx = 1e30f, ly = 1e30f, lz = 1e30f;
    float hx = -1e30f, hy = -1e30f, hz = -1e30f;
    for (int n = tid; n < NPTS; n += 1024) {
        const float* p = zb + (size_t)n * 7;
        float x = p[0], y = p[1], w = p[2];
        lx = fminf(lx, x); hx = fmaxf(hx, x);
        ly = fminf(ly, y); hy = fmaxf(hy, y);
        lz = fminf(lz, w); hz = fmaxf(hz, w);
    }
#pragma unroll
    for (int off = 16; off > 0; off >>= 1) {
        lx = fminf(lx, __shfl_xor_sync(FULL, lx, off));
        ly = fminf(ly, __shfl_xor_sync(FULL, ly, off));
        lz = fminf(lz, __shfl_xor_sync(FULL, lz, off));
        hx = fmaxf(hx, __shfl_xor_sync(FULL, hx, off));
        hy = fmaxf(hy, __shfl_xor_sync(FULL, hy, off));
        hz = fmaxf(hz, __shfl_xor_sync(FULL, hz, off));
    }
    if (lane == 0) {
        swlo[warp][0] = lx; swlo[warp][1] = ly; swlo[warp][2] = lz;
        swhi[warp][0] = hx; swhi[warp][1] = hy; swhi[warp][2] = hz;
    }
    // ---- zero counts (overlap with bbox finishing) ----
    for (int i = tid; i < G3; i += 1024) scnt[i] = 0;
    __syncthreads();
    if (tid == 0) {
        for (int w2 = 1; w2 < 32; w2++) {
            swlo[0][0] = fminf(swlo[0][0], swlo[w2][0]);
            swlo[0][1] = fminf(swlo[0][1], swlo[w2][1]);
            swlo[0][2] = fminf(swlo[0][2], swlo[w2][2]);
            swhi[0][0] = fmaxf(swhi[0][0], swhi[w2][0]);
            swhi[0][1] = fmaxf(swhi[0][1], swhi[w2][1]);
            swhi[0][2] = fmaxf(swhi[0][2], swhi[w2][2]);
        }
        for (int d = 0; d < 3; d++) {
            float span = fmaxf(swhi[0][d] - swlo[0][d], 1e-5f);
            slo3[d]  = swlo[0][d];
            sinv3[d] = (float)GDIM / span;
        }
    }
    __syncthreads();
    const float l0 = slo3[0], l1 = slo3[1], l2 = slo3[2];
    const float i0 = sinv3[0], i1 = sinv3[1], i2 = sinv3[2];

    // ---- count ----
    for (int n = tid; n < NPTS; n += 1024) {
        const float* p = zb + (size_t)n * 7;
        int m = morton3(cell_of(p[0], l0, i0), cell_of(p[1], l1, i1),
                        cell_of(p[2], l2, i2));
        atomicAdd(&scnt[m], 1);
    }
    __syncthreads();

    // ---- exclusive scan (4 cells per thread + block Hillis-Steele) ----
    const int base = tid * 4;
    int c0 = scnt[base], c1 = scnt[base + 1], c2 = scnt[base + 2], c3 = scnt[base + 3];
    int sum = c0 + c1 + c2 + c3;
    ssum[tid] = sum;
    __syncthreads();
    for (int off = 1; off < 1024; off <<= 1) {
        int v = (tid >= off) ? ssum[tid - off] : 0;
        __syncthreads();
        ssum[tid] += v;
        __syncthreads();
    }
    int run = ssum[tid] - sum;
    scnt[base] = run;         run += c0;
    scnt[base + 1] = run;     run += c1;
    scnt[base + 2] = run;     run += c2;
    scnt[base + 3] = run;
    __syncthreads();

    // ---- scatter ----
    for (int n = tid; n < NPTS; n += 1024) {
        const float* p = zb + (size_t)n * 7;
        float x = p[0], y = p[1], w = p[2];
        int m = morton3(cell_of(x, l0, i0), cell_of(y, l1, i1), cell_of(w, l2, i2));
        int pos = atomicAdd(&scnt[m], 1);
        g_pts4[b * NPTS + pos] = make_float4(x, y, w, 0.5f * (x * x + y * y + w * w));
        g_ids [b * NPTS + pos] = n;
    }
    __syncthreads();   // orders our global writes before the reads below

    // ---- chunk bboxes (CHUNK=32: one point per lane) ----
    const float4* pts = g_pts4 + (size_t)b * NPTS;
    for (int ch = warp; ch < NCH; ch += 32) {
        float4 a = pts[ch * CHUNK + lane];
        float blx = a.x, bhx = a.x, bly = a.y, bhy = a.y, blz = a.z, bhz = a.z;
#pragma unroll
        for (int off = 16; off > 0; off >>= 1) {
            blx = fminf(blx, __shfl_xor_sync(FULL, blx, off));
            bly = fminf(bly, __shfl_xor_sync(FULL, bly, off));
            blz = fminf(blz, __shfl_xor_sync(FULL, blz, off));
            bhx = fmaxf(bhx, __shfl_xor_sync(FULL, bhx, off));
            bhy = fmaxf(bhy, __shfl_xor_sync(FULL, bhy, off));
            bhz = fmaxf(bhz, __shfl_xor_sync(FULL, bhz, off));
        }
        if (lane == 0) {
            g_chlo[b][ch] = make_float4(blx, bly, blz, 0.f);
            g_chhi[b][ch] = make_float4(bhx, bhy, bhz, 0.f);
        }
    }
}

// ---------------- kNN query: lockstep scan + chunk-bbox pruning ----------------
// 128 threads = 32 Morton-adjacent queries (lane) x 4 split warps (chunks
// dealt round-robin). Pass 1 scans the home +-1 chunks (seeds tau); pass 2
// walks all other chunks with a per-lane box-distance test + warp ballot
// skip. tau only shrinks, so skipping is exact. score = 0.5|p|^2 - q.p;
// d^2 threshold = 2*tau + |q|^2.
__global__ __launch_bounds__(KTHR) void knn_query_kernel()
{
    __shared__ __align__(16) unsigned char raw[20480];
    __shared__ float tau_sh[32];
    float2 (*cbuf)[KTHR] = (float2 (*)[KTHR])raw;          // 16 KB

    const unsigned FULL = 0xffffffffu;
    const int tid  = threadIdx.x;
    const int lq   = tid & 31;
    const int s    = tid >> 5;
    const int b    = blockIdx.y;
    const int sbase = blockIdx.x * 32;
    const int slot  = sbase + lq;

    const float4* pts = g_pts4 + (size_t)b * NPTS;

    float4 q4 = pts[slot];
    const float qx = q4.x, qy = q4.y, qz = q4.z;
    const float qr2 = 2.0f * q4.w;

    if (tid < 32) tau_sh[tid] = 1e30f;
    __syncthreads();

    float bd[KNN];
    int   bi[KNN];
#pragma unroll
    for (int k = 0; k < KNN; k++) { bd[k] = 1e30f; bi[k] = -1; }

    int   cnt = 0;
    float tau = 1e30f;

#define COMPACT() do {                                                        \
    for (int i = 0; i < cnt; i++) {                                           \
        float2 c = cbuf[i][tid];                                              \
        float d = c.x;                                                        \
        int  id = __float_as_int(c.y);                                        \
        if (d < bd[KNN - 1] && id != slot) {                                  \
            _Pragma("unroll")                                                 \
            for (int k = KNN - 1; k > 0; --k) {                               \
                if (bd[k] > d) {                                              \
                    bool sh = bd[k - 1] > d;                                  \
                    bd[k] = sh ? bd[k - 1] : d;                               \
                    bi[k] = sh ? bi[k - 1] : id;                              \
                }                                                             \
            }                                                                 \
            if (bd[0] > d) { bd[0] = d; bi[0] = id; }                         \
        }                                                                     \
    }                                                                         \
    cnt = 0;                                                                  \
    tau_sh[lq] = fminf(tau_sh[lq], bd[KNN - 1]);                              \
    tau = fminf(bd[KNN - 1], tau_sh[lq]);                                     \
} while (0)

#define SCAN_CHUNK(c) do {                                                    \
    int jb = (c) * CHUNK;                                                     \
    for (int j0 = jb; j0 < jb + CHUNK; j0 += 8) {                             \
        _Pragma("unroll")                                                     \
        for (int u = 0; u < 8; u++) {                                         \
            int j = j0 + u;                                                   \
            float4 t4 = pts[j];                                               \
            float sv = fmaf(-qz, t4.z, t4.w);                                 \
            sv = fmaf(-qy, t4.y, sv);                                         \
            sv = fmaf(-qx, t4.x, sv);                                         \
            if (sv < tau) {                                                   \
                cbuf[cnt][tid] = make_float2(sv, __int_as_float(j));          \
                cnt++;                                                        \
            }                                                                 \
        }                                                                     \
        if (__any_sync(FULL, cnt >= CBUF - 8)) COMPACT();                     \
    }                                                                         \
} while (0)

    // home range (warp-uniform)
    const int h0 = max(sbase / CHUNK - 1, 0);
    const int h1 = min((sbase + 31) / CHUNK + 1, NCH - 1);

    // pass 1: seed tau from home chunks
    for (int c = h0 + s; c <= h1; c += NSPL) SCAN_CHUNK(c);
    COMPACT();
    __syncthreads();                 // seeds visible across split warps
    tau = fminf(bd[KNN - 1], tau_sh[lq]);

    // pass 2: pruned walk over all other chunks
    for (int c = s; c < NCH; c += NSPL) {
        if (c >= h0 && c <= h1) continue;
        float4 lo = g_chlo[b][c];
        float4 hi = g_chhi[b][c];
        float dx = fmaxf(fmaxf(lo.x - qx, qx - hi.x), 0.f);
        float dy = fmaxf(fmaxf(lo.y - qy, qy - hi.y), 0.f);
        float dz = fmaxf(fmaxf(lo.z - qz, qz - hi.z), 0.f);
        float d2box = fmaf(dx, dx, fmaf(dy, dy, dz * dz));
        float thr = fmaf(2.0f, tau, qr2) * 1.0002f;
        if (__any_sync(FULL, d2box < thr)) SCAN_CHUNK(c);
    }
    COMPACT();
#undef SCAN_CHUNK
#undef COMPACT

    __syncthreads();   // reuse raw for the 4-way merge
    float* md = (float*)raw;                         // 80*32*4 = 10240 B
    int*   mi = (int*)(raw + NSPL * KNN * 32 * 4);   // 10240 B
#pragma unroll
    for (int k = 0; k < KNN; k++) {
        md[(s * KNN + k) * 32 + lq] = bd[k];
        mi[(s * KNN + k) * 32 + lq] = bi[k];
    }
    __syncthreads();

    if (tid < 32) {
        float fd[KNN]; int fi[KNN];
#pragma unroll
        for (int k = 0; k < KNN; k++) { fd[k] = 1e30f; fi[k] = -1; }
        for (int i = 0; i < NSPL * KNN; i++) {
            float d = md[i * 32 + tid];
            int  id = mi[i * 32 + tid];
            if (d < fd[KNN - 1]) {
#pragma unroll
                for (int k = KNN - 1; k > 0; --k) {
                    if (fd[k] > d) {
                        bool sh = fd[k - 1] > d;
                        fd[k] = sh ? fd[k - 1] : d;
                        fi[k] = sh ? fi[k - 1] : id;
                    }
                }
                if (fd[0] > d) { fd[0] = d; fi[0] = id; }
            }
        }
        const int* ids = g_ids + (size_t)b * NPTS;
        int myslot = sbase + tid;
        int* o = g_knn + ((size_t)b * NPTS + ids[myslot]) * KNN;
#pragma unroll
        for (int k = 0; k < KNN; k++) o[k] = ids[fi[k]];
    }
}

// ---------------- setup: cond MLP + folded per-batch vectors ----------------
__global__ __launch_bounds__(256) void setup_kernel(
    const float* __restrict__ t, const float* __restrict__ conditioning,
    const float* __restrict__ Wc1, const float* __restrict__ bc1,
    const float* __restrict__ Wc2, const float* __restrict__ bc2,
    const float* __restrict__ Wc3, const float* __restrict__ bc3,
    const float* __restrict__ We1, const float* __restrict__ be1,
    const float* __restrict__ Wn1, const float* __restrict__ bn1)
{
    const unsigned FULL = 0xffffffffu;
    const int tid  = threadIdx.x;
    const int lane = tid & 31;
    const int warp = tid >> 5;

    if (tid < 128) {
        float s1 = 0.f, s2 = 0.f;
#pragma unroll
        for (int c = 0; c < 36; c++) {
            s1 += We1[c * 128 + tid];
            s2 += We1[(36 + c) * 128 + tid];
        }
        g_S1[tid] = s1;
        g_S2[tid] = s2;
    }
    if (tid < 64) {
        float sn = 0.f;
#pragma unroll
        for (int c = 0; c < 36; c++) sn += Wn1[c * 64 + tid];
        g_SN[tid] = sn;
    }

    __shared__ float sc[36], h1[144], h2[144], cv[40];

    for (int b = 0; b < NB; b++) {
        if (tid < 36) {
            float v;
            if (tid < 16) {
                float f = expf(-logf(10000.0f) * (float)tid / 15.0f);
                v = sinf(t[b] * f);
            } else if (tid < 32) {
                int i = tid - 16;
                float f = expf(-logf(10000.0f) * (float)i / 15.0f);
                v = cosf(t[b] * f);
            } else {
                v = conditioning[b * 4 + (tid - 32)];
            }
            sc[tid] = v;
        }
        __syncthreads();
        if (tid < 144) {
            float a = bc1[tid];
#pragma unroll
            for (int c = 0; c < 36; c++) a = fmaf(sc[c], Wc1[c * 144 + tid], a);
            h1[tid] = gelu_f(a);
        }
        __syncthreads();
        for (int o = 0; o < 18; o++) {
            int j = warp + 8 * o;
            float a = 0.f;
#pragma unroll
            for (int r = 0; r < 5; r++) {
                int c = lane + 32 * r;
                if (c < 144) a = fmaf(h1[c], Wc2[c * 144 + j], a);
            }
#pragma unroll
            for (int off = 16; off > 0; off >>= 1)
                a += __shfl_xor_sync(FULL, a, off);
            if (lane == 0) h2[j] = gelu_f(a + bc2[j]);
        }
        __syncthreads();
        for (int o = 0; o < 5; o++) {
            int j = warp + 8 * o;
            if (j < 36) {
                float a = 0.f;
#pragma unroll
                for (int r = 0; r < 5; r++) {
                    int c = lane + 32 * r;
                    if (c < 144) a = fmaf(h2[c], Wc3[c * 36 + j], a);
                }
#pragma unroll
                for (int off = 16; off > 0; off >>= 1)
                    a += __shfl_xor_sync(FULL, a, off);
                if (lane == 0) cv[j] = a + bc3[j];
            }
        }
        __syncthreads();
        if (tid < 128) {
            float a = be1[tid];
#pragma unroll
            for (int c = 0; c < 36; c++)
                a = fmaf(cv[c], We1[c * 128 + tid] + We1[(36 + c) * 128 + tid], a);
            g_base1[b][tid] = a;
        }
        if (tid < 64) {
            float a = bn1[tid];
#pragma unroll
            for (int c = 0; c < 36; c++) a = fmaf(cv[c], Wn1[c * 64 + tid], a);
            g_baseN[b][tid] = a;
        }
        __syncthreads();
    }
}

// ---------------- main: edge MLP + softmax + aggregation + node MLP ----------------
__global__ __launch_bounds__(256) void main_kernel(
    const float* __restrict__ z,
    const float* __restrict__ We1, const float* __restrict__ We2,
    const float* __restrict__ be2,
    const float* __restrict__ Wn1, const float* __restrict__ Wn2,
    const float* __restrict__ bn2,
    const float* __restrict__ alpha, const float* __restrict__ beta,
    float* __restrict__ out)
{
    __shared__ float4 part[8][KNN][17];

    const unsigned FULL = 0xffffffffu;
    const int wlocal = threadIdx.x >> 5;
    const int warp = (blockIdx.x * blockDim.x + threadIdx.x) >> 5;
    const int lane = threadIdx.x & 31;
    const int b = warp >> 13;
    const int n = warp & (NPTS - 1);

    const float* zb = z + (size_t)b * NPTS * 7;
    const float* zt = zb + (size_t)n * 7;
    const float ptx = zt[0], pty = zt[1], ptz = zt[2];
    const float vtx = zt[3], vty = zt[4], vtz = zt[5];
    const float mt  = zt[6];

    float relx = 0.f, rely = 0.f, relz = 0.f;
    float vsx = 0.f, vsy = 0.f, vsz = 0.f;
    float msrc = 0.f, r2 = 0.f, dvv = 0.f, dvr = 0.f, dtr = 0.f;
    if (lane < KNN) {
        int src = g_knn[(size_t)warp * KNN + lane];
        const float* zs = zb + (size_t)src * 7;
        float sx = zs[0], sy = zs[1], sz = zs[2];
        vsx = zs[3]; vsy = zs[4]; vsz = zs[5]; msrc = zs[6];
        relx = sx - ptx; rely = sy - pty; relz = sz - ptz;
        r2  = relx * relx + rely * rely + relz * relz;
        dvv = vsx * vtx + vsy * vty + vsz * vtz;
        dvr = vsx * relx + vsy * rely + vsz * relz;
        dtr = vtx * relx + vty * rely + vtz * relz;
    }

    float s1[4], s2[4], w72[4], w73[4], w74[4], w75[4], b1[4];
    float4 we2[4];
#pragma unroll
    for (int qq = 0; qq < 4; qq++) {
        int j = lane + 32 * qq;
        s1[qq]  = g_S1[j];
        s2[qq]  = g_S2[j];
        w72[qq] = We1[72 * 128 + j];
        w73[qq] = We1[73 * 128 + j];
        w74[qq] = We1[74 * 128 + j];
        w75[qq] = We1[75 * 128 + j];
        b1[qq]  = g_base1[b][j];
        we2[qq] = ((const float4*)We2)[j];
    }

#pragma unroll
    for (int e = 0; e < KNN; e++) {
        float em   = __shfl_sync(FULL, msrc, e);
        float er2  = __shfl_sync(FULL, r2,   e);
        float edvv = __shfl_sync(FULL, dvv,  e);
        float edvr = __shfl_sync(FULL, dvr,  e);
        float edtr = __shfl_sync(FULL, dtr,  e);
        float p0 = 0.f, p1 = 0.f, p2 = 0.f, p3 = 0.f;
#pragma unroll
        for (int qq = 0; qq < 4; qq++) {
            float h = b1[qq];
            h = fmaf(em,   s1[qq],  h);
            h = fmaf(mt,   s2[qq],  h);
            h = fmaf(er2,  w72[qq], h);
            h = fmaf(edvv, w73[qq], h);
            h = fmaf(edvr, w74[qq], h);
            h = fmaf(edtr, w75[qq], h);
            float g = gelu_fast(h);
            p0 = fmaf(g, we2[qq].x, p0);
            p1 = fmaf(g, we2[qq].y, p1);
            p2 = fmaf(g, we2[qq].z, p2);
            p3 = fmaf(g, we2[qq].w, p3);
        }
        p0 += __shfl_xor_sync(FULL, p0, 16);
        p1 += __shfl_xor_sync(FULL, p1, 16);
        p2 += __shfl_xor_sync(FULL, p2, 16);
        p3 += __shfl_xor_sync(FULL, p3, 16);
        if (lane < 16) part[wlocal][e][lane] = make_float4(p0, p1, p2, p3);
    }
    __syncwarp();

    float elog = -1e30f, esmsg = 0.f, ecrel = 0.f, ecvel = 0.f;
    if (lane < KNN) {
        float4 acc = part[wlocal][lane][0];
#pragma unroll
        for (int i = 1; i < 16; i++) {
            float4 p = part[wlocal][lane][i];
            acc.x += p.x; acc.y += p.y; acc.z += p.z; acc.w += p.w;
        }
        elog  = acc.x + be2[0];
        esmsg = acc.y + be2[1];
        ecrel = acc.z + be2[2];
        ecvel = acc.w + be2[3];
    }

    float lg = (lane < KNN) ? elog : -1e30f;
    float mx = lg;
#pragma unroll
    for (int off = 16; off > 0; off >>= 1)
        mx = fmaxf(mx, __shfl_xor_sync(FULL, mx, off));
    float a = (lane < KNN) ? __expf(lg - mx) : 0.f;
    float den = a;
#pragma unroll
    for (int off = 16; off > 0; off >>= 1)
        den += __shfl_xor_sync(FULL, den, off);
    float w = a / den;

    float vmx = w * (ecrel * relx + ecvel * vsx);
    float vmy = w * (ecrel * rely + ecvel * vsy);
    float vmz = w * (ecrel * relz + ecvel * vsz);
    float sg  = w * esmsg;
#pragma unroll
    for (int off = 16; off > 0; off >>= 1) {
        vmx += __shfl_xor_sync(FULL, vmx, off);
        vmy += __shfl_xor_sync(FULL, vmy, off);
        vmz += __shfl_xor_sync(FULL, vmz, off);
        sg  += __shfl_xor_sync(FULL, sg,  off);
    }

    float acc2 = 0.f;
#pragma unroll
    for (int qq = 0; qq < 2; qq++) {
        int j = lane + 32 * qq;
        float h = g_baseN[b][j];
        h = fmaf(mt, g_SN[j], h);
        h = fmaf(sg, Wn1[36 * 64 + j], h);
        acc2 = fmaf(gelu_fast(h), Wn2[j], acc2);
    }
#pragma unroll
    for (int off = 16; off > 0; off >>= 1)
        acc2 += __shfl_xor_sync(FULL, acc2, off);

    if (lane == 0) {
        float sout = acc2 + bn2[0];
        float al = alpha[0], be = beta[0];
        float* o = out + (size_t)warp * 7;
        o[0] = ptx + (ptx + al * vmx);
        o[1] = pty + (pty + al * vmy);
        o[2] = ptz + (ptz + al * vmz);
        o[3] = vtx + be * vmx;
        o[4] = vty + be * vmy;
        o[5] = vtz + be * vmz;
        o[6] = mt + sout;
    }
}

// ---------------- launch ----------------
extern "C" void kernel_launch(void* const* d_in, const int* in_sizes, int n_in,
                              void* d_out, int out_size)
{
    const float* z    = (const float*)d_in[0];
    const float* t    = (const float*)d_in[1];
    const float* cond = (const float*)d_in[2];
    const float* Wc1 = (const float*)d_in[4];
    const float* bc1 = (const float*)d_in[5];
    const float* Wc2 = (const float*)d_in[6];
    const float* bc2 = (const float*)d_in[7];
    const float* Wc3 = (const float*)d_in[8];
    const float* bc3 = (const float*)d_in[9];
    const float* We1 = (const float*)d_in[10];
    const float* be1 = (const float*)d_in[11];
    const float* We2 = (const float*)d_in[12];
    const float* be2 = (const float*)d_in[13];
    const float* Wn1 = (const float*)d_in[14];
    const float* bn1 = (const float*)d_in[15];
    const float* Wn2 = (const float*)d_in[16];
    const float* bn2 = (const float*)d_in[17];
    const float* alpha = (const float*)d_in[18];
    const float* beta  = (const float*)d_in[19];
    float* out = (float*)d_out;

    build_kernel<<<NB, 1024>>>(z);

    dim3 qg(NPTS / 32, NB);
    knn_query_kernel<<<qg, KTHR>>>();

    setup_kernel<<<1, 256>>>(t, cond, Wc1, bc1, Wc2, bc2, Wc3, bc3,
                             We1, be1, Wn1, bn1);

    int total_warps = NB * NPTS;
    int blocks = total_warps / 8;
    main_kernel<<<blocks, 256>>>(z, We1, We2, be2, Wn1, Wn2, bn2,
                                 alpha, beta, out);
}

// round 15
// speedup vs baseline: 1.0891x; 1.0891x over previous
#include <cuda_runtime.h>
#include <math.h>

#define NB    2
#define NPTS  8192
#define KNN   20
#define GDIM  16
#define G3    (GDIM*GDIM*GDIM)
#define CHUNK 64
#define NCH   (NPTS/CHUNK)    // 128
#define NSPL  4
#define KTHR  128
#define CBUF  16

// ---------------- device scratch (no allocation allowed) ----------------
__device__ int    g_knn[NB * NPTS * KNN];
__device__ float  g_S1[128], g_S2[128], g_SN[64];
__device__ float  g_base1[NB][128];
__device__ float  g_baseN[NB][64];
// sorted-point structures
__device__ float4 g_pts4[NB * NPTS];     // Morton-cell-sorted (x,y,z, 0.5*|p|^2)
__device__ int    g_ids [NB * NPTS];
__device__ float4 g_chlo[NB][NCH];
__device__ float4 g_chhi[NB][NCH];

__device__ __forceinline__ float gelu_f(float x) {
    float y = 0.7978845608028654f * (x + 0.044715f * x * x * x);
    float e = __expf(2.0f * y);
    float th = 1.0f - 2.0f / (e + 1.0f);
    return 0.5f * x * (1.0f + th);
}

__device__ __forceinline__ float gelu_fast(float x) {
    float y = 0.7978845608028654f * fmaf(0.044715f * x * x, x, x);
    float t;
    asm("tanh.approx.f32 %0, %1;" : "=f"(t) : "f"(y));
    return 0.5f * x * (1.0f + t);
}

__device__ __forceinline__ int cell_of(float v, float lo, float inv) {
    int i = (int)((v - lo) * inv);
    return i < 0 ? 0 : (i > GDIM - 1 ? GDIM - 1 : i);
}

// 4-bit-per-axis Morton interleave: compact chunks => tight bboxes
__device__ __forceinline__ int morton3(int x, int y, int z) {
    int m = 0;
#pragma unroll
    for (int i = 0; i < 4; i++) {
        m |= (((x >> i) & 1) << (3 * i + 2))
           | (((y >> i) & 1) << (3 * i + 1))
           | (((z >> i) & 1) << (3 * i));
    }
    return m;
}

// ---------------- fused builder: bbox + count + scan + scatter + chunk bboxes ----------------
// one 1024-thread block per batch; counts/scan live in smem. Replaces five
// launch-latency-bound micro-kernels.
__global__ __launch_bounds__(1024) void build_kernel(const float* __restrict__ z)
{
    __shared__ int   scnt[G3];          // 16 KB
    __shared__ int   ssum[1024];        // 4 KB
    __shared__ float swlo[32][3], swhi[32][3];
    __shared__ float slo3[3], sinv3[3];

    const unsigned FULL = 0xffffffffu;
    const int b    = blockIdx.x;
    const int tid  = threadIdx.x;
    const int warp = tid >> 5;
    const int lane = tid & 31;
    const float* zb = z + (size_t)b * NPTS * 7;

    // ---- bbox ----
    float lx = 1e30f, ly = 1e30f, lz = 1e30f;
    float hx = -1e30f, hy = -1e30f, hz = -1e30f;
    for (int n = tid; n < NPTS; n += 1024) {
        const float* p = zb + (size_t)n * 7;
        float x = p[0], y = p[1], w = p[2];
        lx = fminf(lx, x); hx = fmaxf(hx, x);
        ly = fminf(ly, y); hy = fmaxf(hy, y);
        lz = fminf(lz, w); hz = fmaxf(hz, w);
    }
#pragma unroll
    for (int off = 16; off > 0; off >>= 1) {
        lx = fminf(lx, __shfl_xor_sync(FULL, lx, off));
        ly = fminf(ly, __shfl_xor_sync(FULL, ly, off));
        lz = fminf(lz, __shfl_xor_sync(FULL, lz, off));
        hx = fmaxf(hx, __shfl_xor_sync(FULL, hx, off));
        hy = fmaxf(hy, __shfl_xor_sync(FULL, hy, off));
        hz = fmaxf(hz, __shfl_xor_sync(FULL, hz, off));
    }
    if (lane == 0) {
        swlo[warp][0] = lx; swlo[warp][1] = ly; swlo[warp][2] = lz;
        swhi[warp][0] = hx; swhi[warp][1] = hy; swhi[warp][2] = hz;
    }
    // zero counts while bbox settles
    for (int i = tid; i < G3; i += 1024) scnt[i] = 0;
    __syncthreads();
    if (tid == 0) {
        for (int w2 = 1; w2 < 32; w2++) {
            swlo[0][0] = fminf(swlo[0][0], swlo[w2][0]);
            swlo[0][1] = fminf(swlo[0][1], swlo[w2][1]);
            swlo[0][2] = fminf(swlo[0][2], swlo[w2][2]);
            swhi[0][0] = fmaxf(swhi[0][0], swhi[w2][0]);
            swhi[0][1] = fmaxf(swhi[0][1], swhi[w2][1]);
            swhi[0][2] = fmaxf(swhi[0][2], swhi[w2][2]);
        }
        for (int d = 0; d < 3; d++) {
            float span = fmaxf(swhi[0][d] - swlo[0][d], 1e-5f);
            slo3[d]  = swlo[0][d];
            sinv3[d] = (float)GDIM / span;
        }
    }
    __syncthreads();
    const float l0 = slo3[0], l1 = slo3[1], l2 = slo3[2];
    const float i0 = sinv3[0], i1 = sinv3[1], i2 = sinv3[2];

    // ---- count ----
    for (int n = tid; n < NPTS; n += 1024) {
        const float* p = zb + (size_t)n * 7;
        int m = morton3(cell_of(p[0], l0, i0), cell_of(p[1], l1, i1),
                        cell_of(p[2], l2, i2));
        atomicAdd(&scnt[m], 1);
    }
    __syncthreads();

    // ---- exclusive scan (4 cells per thread + block Hillis-Steele) ----
    const int base = tid * 4;
    int c0 = scnt[base], c1 = scnt[base + 1], c2 = scnt[base + 2], c3 = scnt[base + 3];
    int sum = c0 + c1 + c2 + c3;
    ssum[tid] = sum;
    __syncthreads();
    for (int off = 1; off < 1024; off <<= 1) {
        int v = (tid >= off) ? ssum[tid - off] : 0;
        __syncthreads();
        ssum[tid] += v;
        __syncthreads();
    }
    int run = ssum[tid] - sum;
    scnt[base] = run;         run += c0;
    scnt[base + 1] = run;     run += c1;
    scnt[base + 2] = run;     run += c2;
    scnt[base + 3] = run;
    __syncthreads();

    // ---- scatter ----
    for (int n = tid; n < NPTS; n += 1024) {
        const float* p = zb + (size_t)n * 7;
        float x = p[0], y = p[1], w = p[2];
        int m = morton3(cell_of(x, l0, i0), cell_of(y, l1, i1), cell_of(w, l2, i2));
        int pos = atomicAdd(&scnt[m], 1);
        g_pts4[b * NPTS + pos] = make_float4(x, y, w, 0.5f * (x * x + y * y + w * w));
        g_ids [b * NPTS + pos] = n;
    }
    __syncthreads();   // orders our own global writes before reads below

    // ---- chunk bboxes (CHUNK=64: two points per lane) ----
    const float4* pts = g_pts4 + (size_t)b * NPTS;
    for (int ch = warp; ch < NCH; ch += 32) {
        float4 a = pts[ch * CHUNK + lane];
        float4 c = pts[ch * CHUNK + 32 + lane];
        float blx = fminf(a.x, c.x), bhx = fmaxf(a.x, c.x);
        float bly = fminf(a.y, c.y), bhy = fmaxf(a.y, c.y);
        float blz = fminf(a.z, c.z), bhz = fmaxf(a.z, c.z);
#pragma unroll
        for (int off = 16; off > 0; off >>= 1) {
            blx = fminf(blx, __shfl_xor_sync(FULL, blx, off));
            bly = fminf(bly, __shfl_xor_sync(FULL, bly, off));
            blz = fminf(blz, __shfl_xor_sync(FULL, blz, off));
            bhx = fmaxf(bhx, __shfl_xor_sync(FULL, bhx, off));
            bhy = fmaxf(bhy, __shfl_xor_sync(FULL, bhy, off));
            bhz = fmaxf(bhz, __shfl_xor_sync(FULL, bhz, off));
        }
        if (lane == 0) {
            g_chlo[b][ch] = make_float4(blx, bly, blz, 0.f);
            g_chhi[b][ch] = make_float4(bhx, bhy, bhz, 0.f);
        }
    }
}

// ---------------- kNN query: lockstep scan + chunk-bbox pruning ----------------
// 128 threads = 32 Morton-adjacent queries (lane) x 4 split warps (chunks
// dealt round-robin). Pass 1 scans the home +-1 chunks (seeds tau); pass 2
// walks all other chunks with a per-lane box-distance test + warp ballot
// skip. tau only shrinks, so skipping is exact. score = 0.5|p|^2 - q.p;
// d^2 threshold = 2*tau + |q|^2.
__global__ __launch_bounds__(KTHR) void knn_query_kernel()
{
    __shared__ __align__(16) unsigned char raw[20480];
    __shared__ float tau_sh[32];
    float2 (*cbuf)[KTHR] = (float2 (*)[KTHR])raw;          // 16 KB

    const unsigned FULL = 0xffffffffu;
    const int tid  = threadIdx.x;
    const int lq   = tid & 31;
    const int s    = tid >> 5;
    const int b    = blockIdx.y;
    const int sbase = blockIdx.x * 32;
    const int slot  = sbase + lq;

    const float4* pts = g_pts4 + (size_t)b * NPTS;

    float4 q4 = pts[slot];
    const float qx = q4.x, qy = q4.y, qz = q4.z;
    const float qr2 = 2.0f * q4.w;

    if (tid < 32) tau_sh[tid] = 1e30f;
    __syncthreads();

    float bd[KNN];
    int   bi[KNN];
#pragma unroll
    for (int k = 0; k < KNN; k++) { bd[k] = 1e30f; bi[k] = -1; }

    int   cnt = 0;
    float tau = 1e30f;

#define COMPACT() do {                                                        \
    for (int i = 0; i < cnt; i++) {                                           \
        float2 c = cbuf[i][tid];                                              \
        float d = c.x;                                                        \
        int  id = __float_as_int(c.y);                                        \
        if (d < bd[KNN - 1] && id != slot) {                                  \
            _Pragma("unroll")                                                 \
            for (int k = KNN - 1; k > 0; --k) {                               \
                if (bd[k] > d) {                                              \
                    bool sh = bd[k - 1] > d;                                  \
                    bd[k] = sh ? bd[k - 1] : d;                               \
                    bi[k] = sh ? bi[k - 1] : id;                              \
                }                                                             \
            }                                                                 \
            if (bd[0] > d) { bd[0] = d; bi[0] = id; }                         \
        }                                                                     \
    }                                                                         \
    cnt = 0;                                                                  \
    tau_sh[lq] = fminf(tau_sh[lq], bd[KNN - 1]);                              \
    tau = fminf(bd[KNN - 1], tau_sh[lq]);                                     \
} while (0)

#define SCAN_CHUNK(c) do {                                                    \
    int jb = (c) * CHUNK;                                                     \
    for (int j0 = jb; j0 < jb + CHUNK; j0 += 8) {                             \
        _Pragma("unroll")                                                     \
        for (int u = 0; u < 8; u++) {                                         \
            int j = j0 + u;                                                   \
            float4 t4 = pts[j];                                               \
            float sv = fmaf(-qz, t4.z, t4.w);                                 \
            sv = fmaf(-qy, t4.y, sv);                                         \
            sv = fmaf(-qx, t4.x, sv);                                         \
            if (sv < tau) {                                                   \
                cbuf[cnt][tid] = make_float2(sv, __int_as_float(j));          \
                cnt++;                                                        \
            }                                                                 \
        }                                                                     \
        if (__any_sync(FULL, cnt >= CBUF - 8)) COMPACT();                     \
    }                                                                         \
} while (0)

    // home range (warp-uniform)
    const int h0 = max(sbase / CHUNK - 1, 0);
    const int h1 = min((sbase + 31) / CHUNK + 1, NCH - 1);

    // pass 1: seed tau from home chunks
    for (int c = h0 + s; c <= h1; c += NSPL) SCAN_CHUNK(c);
    COMPACT();
    __syncthreads();                 // seeds visible across split warps
    tau = fminf(bd[KNN - 1], tau_sh[lq]);

    // pass 2: pruned walk over all other chunks
    for (int c = s; c < NCH; c += NSPL) {
        if (c >= h0 && c <= h1) continue;
        float4 lo = g_chlo[b][c];
        float4 hi = g_chhi[b][c];
        float dx = fmaxf(fmaxf(lo.x - qx, qx - hi.x), 0.f);
        float dy = fmaxf(fmaxf(lo.y - qy, qy - hi.y), 0.f);
        float dz = fmaxf(fmaxf(lo.z - qz, qz - hi.z), 0.f);
        float d2box = fmaf(dx, dx, fmaf(dy, dy, dz * dz));
        float thr = fmaf(2.0f, tau, qr2) * 1.0002f;
        if (__any_sync(FULL, d2box < thr)) SCAN_CHUNK(c);
    }
    COMPACT();
#undef SCAN_CHUNK
#undef COMPACT

    __syncthreads();   // reuse raw for the 4-way merge
    float* md = (float*)raw;                         // 80*32*4 = 10240 B
    int*   mi = (int*)(raw + NSPL * KNN * 32 * 4);   // 10240 B
#pragma unroll
    for (int k = 0; k < KNN; k++) {
        md[(s * KNN + k) * 32 + lq] = bd[k];
        mi[(s * KNN + k) * 32 + lq] = bi[k];
    }
    __syncthreads();

    if (tid < 32) {
        float fd[KNN]; int fi[KNN];
#pragma unroll
        for (int k = 0; k < KNN; k++) { fd[k] = 1e30f; fi[k] = -1; }
        for (int i = 0; i < NSPL * KNN; i++) {
            float d = md[i * 32 + tid];
            int  id = mi[i * 32 + tid];
            if (d < fd[KNN - 1]) {
#pragma unroll
                for (int k = KNN - 1; k > 0; --k) {
                    if (fd[k] > d) {
                        bool sh = fd[k - 1] > d;
                        fd[k] = sh ? fd[k - 1] : d;
                        fi[k] = sh ? fi[k - 1] : id;
                    }
                }
                if (fd[0] > d) { fd[0] = d; fi[0] = id; }
            }
        }
        const int* ids = g_ids + (size_t)b * NPTS;
        int myslot = sbase + tid;
        int* o = g_knn + ((size_t)b * NPTS + ids[myslot]) * KNN;
#pragma unroll
        for (int k = 0; k < KNN; k++) o[k] = ids[fi[k]];
    }
}

// ---------------- setup: cond MLP + folded per-batch vectors ----------------
__global__ __launch_bounds__(256) void setup_kernel(
    const float* __restrict__ t, const float* __restrict__ conditioning,
    const float* __restrict__ Wc1, const float* __restrict__ bc1,
    const float* __restrict__ Wc2, const float* __restrict__ bc2,
    const float* __restrict__ Wc3, const float* __restrict__ bc3,
    const float* __restrict__ We1, const float* __restrict__ be1,
    const float* __restrict__ Wn1, const float* __restrict__ bn1)
{
    const unsigned FULL = 0xffffffffu;
    const int tid  = threadIdx.x;
    const int lane = tid & 31;
    const int warp = tid >> 5;

    if (tid < 128) {
        float s1 = 0.f, s2 = 0.f;
#pragma unroll
        for (int c = 0; c < 36; c++) {
            s1 += We1[c * 128 + tid];
            s2 += We1[(36 + c) * 128 + tid];
        }
        g_S1[tid] = s1;
        g_S2[tid] = s2;
    }
    if (tid < 64) {
        float sn = 0.f;
#pragma unroll
        for (int c = 0; c < 36; c++) sn += Wn1[c * 64 + tid];
        g_SN[tid] = sn;
    }

    __shared__ float sc[36], h1[144], h2[144], cv[40];

    for (int b = 0; b < NB; b++) {
        if (tid < 36) {
            float v;
            if (tid < 16) {
                float f = expf(-logf(10000.0f) * (float)tid / 15.0f);
                v = sinf(t[b] * f);
            } else if (tid < 32) {
                int i = tid - 16;
                float f = expf(-logf(10000.0f) * (float)i / 15.0f);
                v = cosf(t[b] * f);
            } else {
                v = conditioning[b * 4 + (tid - 32)];
            }
            sc[tid] = v;
        }
        __syncthreads();
        if (tid < 144) {
            float a = bc1[tid];
#pragma unroll
            for (int c = 0; c < 36; c++) a = fmaf(sc[c], Wc1[c * 144 + tid], a);
            h1[tid] = gelu_f(a);
        }
        __syncthreads();
        for (int o = 0; o < 18; o++) {
            int j = warp + 8 * o;
            float a = 0.f;
#pragma unroll
            for (int r = 0; r < 5; r++) {
                int c = lane + 32 * r;
                if (c < 144) a = fmaf(h1[c], Wc2[c * 144 + j], a);
            }
#pragma unroll
            for (int off = 16; off > 0; off >>= 1)
                a += __shfl_xor_sync(FULL, a, off);
            if (lane == 0) h2[j] = gelu_f(a + bc2[j]);
        }
        __syncthreads();
        for (int o = 0; o < 5; o++) {
            int j = warp + 8 * o;
            if (j < 36) {
                float a = 0.f;
#pragma unroll
                for (int r = 0; r < 5; r++) {
                    int c = lane + 32 * r;
                    if (c < 144) a = fmaf(h2[c], Wc3[c * 36 + j], a);
                }
#pragma unroll
                for (int off = 16; off > 0; off >>= 1)
                    a += __shfl_xor_sync(FULL, a, off);
                if (lane == 0) cv[j] = a + bc3[j];
            }
        }
        __syncthreads();
        if (tid < 128) {
            float a = be1[tid];
#pragma unroll
            for (int c = 0; c < 36; c++)
                a = fmaf(cv[c], We1[c * 128 + tid] + We1[(36 + c) * 128 + tid], a);
            g_base1[b][tid] = a;
        }
        if (tid < 64) {
            float a = bn1[tid];
#pragma unroll
            for (int c = 0; c < 36; c++) a = fmaf(cv[c], Wn1[c * 64 + tid], a);
            g_baseN[b][tid] = a;
        }
        __syncthreads();
    }
}

// ---------------- main: edge MLP + softmax + aggregation + node MLP ----------------
__global__ __launch_bounds__(256) void main_kernel(
    const float* __restrict__ z,
    const float* __restrict__ We1, const float* __restrict__ We2,
    const float* __restrict__ be2,
    const float* __restrict__ Wn1, const float* __restrict__ Wn2,
    const float* __restrict__ bn2,
    const float* __restrict__ alpha, const float* __restrict__ beta,
    float* __restrict__ out)
{
    __shared__ float4 part[8][KNN][17];

    const unsigned FULL = 0xffffffffu;
    const int wlocal = threadIdx.x >> 5;
    const int warp = (blockIdx.x * blockDim.x + threadIdx.x) >> 5;
    const int lane = threadIdx.x & 31;
    const int b = warp >> 13;
    const int n = warp & (NPTS - 1);

    const float* zb = z + (size_t)b * NPTS * 7;
    const float* zt = zb + (size_t)n * 7;
    const float ptx = zt[0], pty = zt[1], ptz = zt[2];
    const float vtx = zt[3], vty = zt[4], vtz = zt[5];
    const float mt  = zt[6];

    float relx = 0.f, rely = 0.f, relz = 0.f;
    float vsx = 0.f, vsy = 0.f, vsz = 0.f;
    float msrc = 0.f, r2 = 0.f, dvv = 0.f, dvr = 0.f, dtr = 0.f;
    if (lane < KNN) {
        int src = g_knn[(size_t)warp * KNN + lane];
        const float* zs = zb + (size_t)src * 7;
        float sx = zs[0], sy = zs[1], sz = zs[2];
        vsx = zs[3]; vsy = zs[4]; vsz = zs[5]; msrc = zs[6];
        relx = sx - ptx; rely = sy - pty; relz = sz - ptz;
        r2  = relx * relx + rely * rely + relz * relz;
        dvv = vsx * vtx + vsy * vty + vsz * vtz;
        dvr = vsx * relx + vsy * rely + vsz * relz;
        dtr = vtx * relx + vty * rely + vtz * relz;
    }

    float s1[4], s2[4], w72[4], w73[4], w74[4], w75[4], b1[4];
    float4 we2[4];
#pragma unroll
    for (int qq = 0; qq < 4; qq++) {
        int j = lane + 32 * qq;
        s1[qq]  = g_S1[j];
        s2[qq]  = g_S2[j];
        w72[qq] = We1[72 * 128 + j];
        w73[qq] = We1[73 * 128 + j];
        w74[qq] = We1[74 * 128 + j];
        w75[qq] = We1[75 * 128 + j];
        b1[qq]  = g_base1[b][j];
        we2[qq] = ((const float4*)We2)[j];
    }

#pragma unroll
    for (int e = 0; e < KNN; e++) {
        float em   = __shfl_sync(FULL, msrc, e);
        float er2  = __shfl_sync(FULL, r2,   e);
        float edvv = __shfl_sync(FULL, dvv,  e);
        float edvr = __shfl_sync(FULL, dvr,  e);
        float edtr = __shfl_sync(FULL, dtr,  e);
        float p0 = 0.f, p1 = 0.f, p2 = 0.f, p3 = 0.f;
#pragma unroll
        for (int qq = 0; qq < 4; qq++) {
            float h = b1[qq];
            h = fmaf(em,   s1[qq],  h);
            h = fmaf(mt,   s2[qq],  h);
            h = fmaf(er2,  w72[qq], h);
            h = fmaf(edvv, w73[qq], h);
            h = fmaf(edvr, w74[qq], h);
            h = fmaf(edtr, w75[qq], h);
            float g = gelu_fast(h);
            p0 = fmaf(g, we2[qq].x, p0);
            p1 = fmaf(g, we2[qq].y, p1);
            p2 = fmaf(g, we2[qq].z, p2);
            p3 = fmaf(g, we2[qq].w, p3);
        }
        p0 += __shfl_xor_sync(FULL, p0, 16);
        p1 += __shfl_xor_sync(FULL, p1, 16);
        p2 += __shfl_xor_sync(FULL, p2, 16);
        p3 += __shfl_xor_sync(FULL, p3, 16);
        if (lane < 16) part[wlocal][e][lane] = make_float4(p0, p1, p2, p3);
    }
    __syncwarp();

    float elog = -1e30f, esmsg = 0.f, ecrel = 0.f, ecvel = 0.f;
    if (lane < KNN) {
        float4 acc = part[wlocal][lane][0];
#pragma unroll
        for (int i = 1; i < 16; i++) {
            float4 p = part[wlocal][lane][i];
            acc.x += p.x; acc.y += p.y; acc.z += p.z; acc.w += p.w;
        }
        elog  = acc.x + be2[0];
        esmsg = acc.y + be2[1];
        ecrel = acc.z + be2[2];
        ecvel = acc.w + be2[3];
    }

    float lg = (lane < KNN) ? elog : -1e30f;
    float mx = lg;
#pragma unroll
    for (int off = 16; off > 0; off >>= 1)
        mx = fmaxf(mx, __shfl_xor_sync(FULL, mx, off));
    float a = (lane < KNN) ? __expf(lg - mx) : 0.f;
    float den = a;
#pragma unroll
    for (int off = 16; off > 0; off >>= 1)
        den += __shfl_xor_sync(FULL, den, off);
    float w = a / den;

    float vmx = w * (ecrel * relx + ecvel * vsx);
    float vmy = w * (ecrel * rely + ecvel * vsy);
    float vmz = w * (ecrel * relz + ecvel * vsz);
    float sg  = w * esmsg;
#pragma unroll
    for (int off = 16; off > 0; off >>= 1) {
        vmx += __shfl_xor_sync(FULL, vmx, off);
        vmy += __shfl_xor_sync(FULL, vmy, off);
        vmz += __shfl_xor_sync(FULL, vmz, off);
        sg  += __shfl_xor_sync(FULL, sg,  off);
    }

    float acc2 = 0.f;
#pragma unroll
    for (int qq = 0; qq < 2; qq++) {
        int j = lane + 32 * qq;
        float h = g_baseN[b][j];
        h = fmaf(mt, g_SN[j], h);
        h = fmaf(sg, Wn1[36 * 64 + j], h);
        acc2 = fmaf(gelu_fast(h), Wn2[j], acc2);
    }
#pragma unroll
    for (int off = 16; off > 0; off >>= 1)
        acc2 += __shfl_xor_sync(FULL, acc2, off);

    if (lane == 0) {
        float sout = acc2 + bn2[0];
        float al = alpha[0], be = beta[0];
        float* o = out + (size_t)warp * 7;
        o[0] = ptx + (ptx + al * vmx);
        o[1] = pty + (pty + al * vmy);
        o[2] = ptz + (ptz + al * vmz);
        o[3] = vtx + be * vmx;
        o[4] = vty + be * vmy;
        o[5] = vtz + be * vmz;
        o[6] = mt + sout;
    }
}

// ---------------- launch ----------------
extern "C" void kernel_launch(void* const* d_in, const int* in_sizes, int n_in,
                              void* d_out, int out_size)
{
    const float* z    = (const float*)d_in[0];
    const float* t    = (const float*)d_in[1];
    const float* cond = (const float*)d_in[2];
    const float* Wc1 = (const float*)d_in[4];
    const float* bc1 = (const float*)d_in[5];
    const float* Wc2 = (const float*)d_in[6];
    const float* bc2 = (const float*)d_in[7];
    const float* Wc3 = (const float*)d_in[8];
    const float* bc3 = (const float*)d_in[9];
    const float* We1 = (const float*)d_in[10];
    const float* be1 = (const float*)d_in[11];
    const float* We2 = (const float*)d_in[12];
    const float* be2 = (const float*)d_in[13];
    const float* Wn1 = (const float*)d_in[14];
    const float* bn1 = (const float*)d_in[15];
    const float* Wn2 = (const float*)d_in[16];
    const float* bn2 = (const float*)d_in[17];
    const float* alpha = (const float*)d_in[18];
    const float* beta  = (const float*)d_in[19];
    float* out = (float*)d_out;

    build_kernel<<<NB, 1024>>>(z);

    dim3 qg(NPTS / 32, NB);
    knn_query_kernel<<<qg, KTHR>>>();

    setup_kernel<<<1, 256>>>(t, cond, Wc1, bc1, Wc2, bc2, Wc3, bc3,
                             We1, be1, Wn1, bn1);

    int total_warps = NB * NPTS;
    int blocks = total_warps / 8;
    main_kernel<<<blocks, 256>>>(z, We1, We2, be2, Wn1, Wn2, bn2,
                                 alpha, beta, out);
}

// round 16
// speedup vs baseline: 1.3231x; 1.2149x over previous
#include <cuda_runtime.h>
#include <math.h>

#define NB    2
#define NPTS  8192
#define KNN   20
#define GDIM  16
#define G3    (GDIM*GDIM*GDIM)
#define CHUNK 64
#define NCH   (NPTS/CHUNK)    // 128
#define NSPL  4
#define KTHR  128
#define CBUF  16

// ---------------- device scratch (no allocation allowed) ----------------
__device__ int    g_knn[NB * NPTS * KNN];
__device__ float  g_S1[128], g_S2[128], g_SN[64];
__device__ float  g_base1[NB][128];
__device__ float  g_baseN[NB][64];
// sorted-point structures
__device__ float4 g_pts4[NB * NPTS];     // Morton-cell-sorted (x,y,z, 0.5*|p|^2)
__device__ int    g_ids [NB * NPTS];
__device__ float4 g_chlo[NB][NCH];
__device__ float4 g_chhi[NB][NCH];

__device__ __forceinline__ float gelu_f(float x) {
    float y = 0.7978845608028654f * (x + 0.044715f * x * x * x);
    float e = __expf(2.0f * y);
    float th = 1.0f - 2.0f / (e + 1.0f);
    return 0.5f * x * (1.0f + th);
}

__device__ __forceinline__ float gelu_fast(float x) {
    float y = 0.7978845608028654f * fmaf(0.044715f * x * x, x, x);
    float t;
    asm("tanh.approx.f32 %0, %1;" : "=f"(t) : "f"(y));
    return 0.5f * x * (1.0f + t);
}

__device__ __forceinline__ int cell_of(float v, float lo, float inv) {
    int i = (int)((v - lo) * inv);
    return i < 0 ? 0 : (i > GDIM - 1 ? GDIM - 1 : i);
}

// 4-bit-per-axis Morton interleave: compact chunks => tight bboxes
__device__ __forceinline__ int morton3(int x, int y, int z) {
    int m = 0;
#pragma unroll
    for (int i = 0; i < 4; i++) {
        m |= (((x >> i) & 1) << (3 * i + 2))
           | (((y >> i) & 1) << (3 * i + 1))
           | (((z >> i) & 1) << (3 * i));
    }
    return m;
}

// ---------------- fused builder + setup ----------------
// grid = NB+1 blocks of 1024 threads.
//   blocks 0..NB-1 : per-batch Morton grid build (bbox/count/scan/scatter/chunk bboxes)
//   block NB       : cond-MLP setup (runs in parallel on another SM)
__global__ __launch_bounds__(1024) void build_kernel(
    const float* __restrict__ z,
    const float* __restrict__ t, const float* __restrict__ conditioning,
    const float* __restrict__ Wc1, const float* __restrict__ bc1,
    const float* __restrict__ Wc2, const float* __restrict__ bc2,
    const float* __restrict__ Wc3, const float* __restrict__ bc3,
    const float* __restrict__ We1, const float* __restrict__ be1,
    const float* __restrict__ Wn1, const float* __restrict__ bn1)
{
    __shared__ int   scnt[G3];          // 16 KB (build blocks)
    __shared__ int   ssum[1024];        // 4 KB
    __shared__ float swlo[32][3], swhi[32][3];
    __shared__ float slo3[3], sinv3[3];
    __shared__ float sc[36], h1[144], h2[144], cv[40];   // setup block

    const unsigned FULL = 0xffffffffu;
    const int tid  = threadIdx.x;
    const int warp = tid >> 5;
    const int lane = tid & 31;

    if (blockIdx.x == NB) {
        // ================= setup block =================
        if (tid < 128) {
            float s1 = 0.f, s2 = 0.f;
#pragma unroll
            for (int c = 0; c < 36; c++) {
                s1 += We1[c * 128 + tid];
                s2 += We1[(36 + c) * 128 + tid];
            }
            g_S1[tid] = s1;
            g_S2[tid] = s2;
        }
        if (tid < 64) {
            float sn = 0.f;
#pragma unroll
            for (int c = 0; c < 36; c++) sn += Wn1[c * 64 + tid];
            g_SN[tid] = sn;
        }

        for (int b = 0; b < NB; b++) {
            if (tid < 36) {
                float v;
                if (tid < 16) {
                    float f = expf(-logf(10000.0f) * (float)tid / 15.0f);
                    v = sinf(t[b] * f);
                } else if (tid < 32) {
                    int i = tid - 16;
                    float f = expf(-logf(10000.0f) * (float)i / 15.0f);
                    v = cosf(t[b] * f);
                } else {
                    v = conditioning[b * 4 + (tid - 32)];
                }
                sc[tid] = v;
            }
            __syncthreads();
            if (tid < 144) {
                float a = bc1[tid];
#pragma unroll
                for (int c = 0; c < 36; c++) a = fmaf(sc[c], Wc1[c * 144 + tid], a);
                h1[tid] = gelu_f(a);
            }
            __syncthreads();
            // h2: 144 outputs over 32 warps (<=5 per warp), 144-term dots
#pragma unroll
            for (int o = 0; o < 5; o++) {
                int j = warp + 32 * o;
                if (j < 144) {
                    float a = 0.f;
#pragma unroll
                    for (int r = 0; r < 5; r++) {
                        int c = lane + 32 * r;
                        if (c < 144) a = fmaf(h1[c], Wc2[c * 144 + j], a);
                    }
#pragma unroll
                    for (int off = 16; off > 0; off >>= 1)
                        a += __shfl_xor_sync(FULL, a, off);
                    if (lane == 0) h2[j] = gelu_f(a + bc2[j]);
                }
            }
            __syncthreads();
            // cv: 36 outputs over 32 warps
#pragma unroll
            for (int o = 0; o < 2; o++) {
                int j = warp + 32 * o;
                if (j < 36) {
                    float a = 0.f;
#pragma unroll
                    for (int r = 0; r < 5; r++) {
                        int c = lane + 32 * r;
                        if (c < 144) a = fmaf(h2[c], Wc3[c * 36 + j], a);
                    }
#pragma unroll
                    for (int off = 16; off > 0; off >>= 1)
                        a += __shfl_xor_sync(FULL, a, off);
                    if (lane == 0) cv[j] = a + bc3[j];
                }
            }
            __syncthreads();
            if (tid < 128) {
                float a = be1[tid];
#pragma unroll
                for (int c = 0; c < 36; c++)
                    a = fmaf(cv[c], We1[c * 128 + tid] + We1[(36 + c) * 128 + tid], a);
                g_base1[b][tid] = a;
            }
            if (tid < 64) {
                float a = bn1[tid];
#pragma unroll
                for (int c = 0; c < 36; c++) a = fmaf(cv[c], Wn1[c * 64 + tid], a);
                g_baseN[b][tid] = a;
            }
            __syncthreads();
        }
        return;
    }

    // ================= grid build blocks =================
    const int b = blockIdx.x;
    const float* zb = z + (size_t)b * NPTS * 7;

    // ---- bbox ----
    float lx = 1e30f, ly = 1e30f, lz = 1e30f;
    float hx = -1e30f, hy = -1e30f, hz = -1e30f;
    for (int n = tid; n < NPTS; n += 1024) {
        const float* p = zb + (size_t)n * 7;
        float x = p[0], y = p[1], w = p[2];
        lx = fminf(lx, x); hx = fmaxf(hx, x);
        ly = fminf(ly, y); hy = fmaxf(hy, y);
        lz = fminf(lz, w); hz = fmaxf(hz, w);
    }
#pragma unroll
    for (int off = 16; off > 0; off >>= 1) {
        lx = fminf(lx, __shfl_xor_sync(FULL, lx, off));
        ly = fminf(ly, __shfl_xor_sync(FULL, ly, off));
        lz = fminf(lz, __shfl_xor_sync(FULL, lz, off));
        hx = fmaxf(hx, __shfl_xor_sync(FULL, hx, off));
        hy = fmaxf(hy, __shfl_xor_sync(FULL, hy, off));
        hz = fmaxf(hz, __shfl_xor_sync(FULL, hz, off));
    }
    if (lane == 0) {
        swlo[warp][0] = lx; swlo[warp][1] = ly; swlo[warp][2] = lz;
        swhi[warp][0] = hx; swhi[warp][1] = hy; swhi[warp][2] = hz;
    }
    for (int i = tid; i < G3; i += 1024) scnt[i] = 0;
    __syncthreads();
    if (tid == 0) {
        for (int w2 = 1; w2 < 32; w2++) {
            swlo[0][0] = fminf(swlo[0][0], swlo[w2][0]);
            swlo[0][1] = fminf(swlo[0][1], swlo[w2][1]);
            swlo[0][2] = fminf(swlo[0][2], swlo[w2][2]);
            swhi[0][0] = fmaxf(swhi[0][0], swhi[w2][0]);
            swhi[0][1] = fmaxf(swhi[0][1], swhi[w2][1]);
            swhi[0][2] = fmaxf(swhi[0][2], swhi[w2][2]);
        }
        for (int d = 0; d < 3; d++) {
            float span = fmaxf(swhi[0][d] - swlo[0][d], 1e-5f);
            slo3[d]  = swlo[0][d];
            sinv3[d] = (float)GDIM / span;
        }
    }
    __syncthreads();
    const float l0 = slo3[0], l1 = slo3[1], l2 = slo3[2];
    const float i0 = sinv3[0], i1 = sinv3[1], i2 = sinv3[2];

    // ---- count ----
    for (int n = tid; n < NPTS; n += 1024) {
        const float* p = zb + (size_t)n * 7;
        int m = morton3(cell_of(p[0], l0, i0), cell_of(p[1], l1, i1),
                        cell_of(p[2], l2, i2));
        atomicAdd(&scnt[m], 1);
    }
    __syncthreads();

    // ---- exclusive scan (4 cells per thread + block Hillis-Steele) ----
    const int base = tid * 4;
    int c0 = scnt[base], c1 = scnt[base + 1], c2 = scnt[base + 2], c3 = scnt[base + 3];
    int sum = c0 + c1 + c2 + c3;
    ssum[tid] = sum;
    __syncthreads();
    for (int off = 1; off < 1024; off <<= 1) {
        int v = (tid >= off) ? ssum[tid - off] : 0;
        __syncthreads();
        ssum[tid] += v;
        __syncthreads();
    }
    int run = ssum[tid] - sum;
    scnt[base] = run;         run += c0;
    scnt[base + 1] = run;     run += c1;
    scnt[base + 2] = run;     run += c2;
    scnt[base + 3] = run;
    __syncthreads();

    // ---- scatter ----
    for (int n = tid; n < NPTS; n += 1024) {
        const float* p = zb + (size_t)n * 7;
        float x = p[0], y = p[1], w = p[2];
        int m = morton3(cell_of(x, l0, i0), cell_of(y, l1, i1), cell_of(w, l2, i2));
        int pos = atomicAdd(&scnt[m], 1);
        g_pts4[b * NPTS + pos] = make_float4(x, y, w, 0.5f * (x * x + y * y + w * w));
        g_ids [b * NPTS + pos] = n;
    }
    __syncthreads();   // orders our own global writes before reads below

    // ---- chunk bboxes (CHUNK=64: two points per lane) ----
    const float4* pts = g_pts4 + (size_t)b * NPTS;
    for (int ch = warp; ch < NCH; ch += 32) {
        float4 a = pts[ch * CHUNK + lane];
        float4 c = pts[ch * CHUNK + 32 + lane];
        float blx = fminf(a.x, c.x), bhx = fmaxf(a.x, c.x);
        float bly = fminf(a.y, c.y), bhy = fmaxf(a.y, c.y);
        float blz = fminf(a.z, c.z), bhz = fmaxf(a.z, c.z);
#pragma unroll
        for (int off = 16; off > 0; off >>= 1) {
            blx = fminf(blx, __shfl_xor_sync(FULL, blx, off));
            bly = fminf(bly, __shfl_xor_sync(FULL, bly, off));
            blz = fminf(blz, __shfl_xor_sync(FULL, blz, off));
            bhx = fmaxf(bhx, __shfl_xor_sync(FULL, bhx, off));
            bhy = fmaxf(bhy, __shfl_xor_sync(FULL, bhy, off));
            bhz = fmaxf(bhz, __shfl_xor_sync(FULL, bhz, off));
        }
        if (lane == 0) {
            g_chlo[b][ch] = make_float4(blx, bly, blz, 0.f);
            g_chhi[b][ch] = make_float4(bhx, bhy, bhz, 0.f);
        }
    }
}

// ---------------- kNN query: lockstep scan + chunk-bbox pruning ----------------
// 128 threads = 32 Morton-adjacent queries (lane) x 4 split warps (chunks
// dealt round-robin). Pass 1 scans the home +-1 chunks (seeds tau); pass 2
// walks all other chunks with a per-lane box-distance test + warp ballot
// skip. tau only shrinks, so skipping is exact. score = 0.5|p|^2 - q.p;
// d^2 threshold = 2*tau + |q|^2.
__global__ __launch_bounds__(KTHR) void knn_query_kernel()
{
    __shared__ __align__(16) unsigned char raw[20480];
    __shared__ float tau_sh[32];
    float2 (*cbuf)[KTHR] = (float2 (*)[KTHR])raw;          // 16 KB

    const unsigned FULL = 0xffffffffu;
    const int tid  = threadIdx.x;
    const int lq   = tid & 31;
    const int s    = tid >> 5;
    const int b    = blockIdx.y;
    const int sbase = blockIdx.x * 32;
    const int slot  = sbase + lq;

    const float4* pts = g_pts4 + (size_t)b * NPTS;

    float4 q4 = pts[slot];
    const float qx = q4.x, qy = q4.y, qz = q4.z;
    const float qr2 = 2.0f * q4.w;

    if (tid < 32) tau_sh[tid] = 1e30f;
    __syncthreads();

    float bd[KNN];
    int   bi[KNN];
#pragma unroll
    for (int k = 0; k < KNN; k++) { bd[k] = 1e30f; bi[k] = -1; }

    int   cnt = 0;
    float tau = 1e30f;

#define COMPACT() do {                                                        \
    for (int i = 0; i < cnt; i++) {                                           \
        float2 c = cbuf[i][tid];                                              \
        float d = c.x;                                                        \
        int  id = __float_as_int(c.y);                                        \
        if (d < bd[KNN - 1] && id != slot) {                                  \
            _Pragma("unroll")                                                 \
            for (int k = KNN - 1; k > 0; --k) {                               \
                if (bd[k] > d) {                                              \
                    bool sh = bd[k - 1] > d;                                  \
                    bd[k] = sh ? bd[k - 1] : d;                               \
                    bi[k] = sh ? bi[k - 1] : id;                              \
                }                                                             \
            }                                                                 \
            if (bd[0] > d) { bd[0] = d; bi[0] = id; }                         \
        }                                                                     \
    }                                                                         \
    cnt = 0;                                                                  \
    tau_sh[lq] = fminf(tau_sh[lq], bd[KNN - 1]);                              \
    tau = fminf(bd[KNN - 1], tau_sh[lq]);                                     \
} while (0)

#define SCAN_CHUNK(c) do {                                                    \
    int jb = (c) * CHUNK;                                                     \
    for (int j0 = jb; j0 < jb + CHUNK; j0 += 8) {                             \
        _Pragma("unroll")                                                     \
        for (int u = 0; u < 8; u++) {                                         \
            int j = j0 + u;                                                   \
            float4 t4 = pts[j];                                               \
            float sv = fmaf(-qz, t4.z, t4.w);                                 \
            sv = fmaf(-qy, t4.y, sv);                                         \
            sv = fmaf(-qx, t4.x, sv);                                         \
            if (sv < tau) {                                                   \
                cbuf[cnt][tid] = make_float2(sv, __int_as_float(j));          \
                cnt++;                                                        \
            }                                                                 \
        }                                                                     \
        if (__any_sync(FULL, cnt >= CBUF - 8)) COMPACT();                     \
    }                                                                         \
} while (0)

    // home range (warp-uniform)
    const int h0 = max(sbase / CHUNK - 1, 0);
    const int h1 = min((sbase + 31) / CHUNK + 1, NCH - 1);

    // pass 1: seed tau from home chunks
    for (int c = h0 + s; c <= h1; c += NSPL) SCAN_CHUNK(c);
    COMPACT();
    __syncthreads();                 // seeds visible across split warps
    tau = fminf(bd[KNN - 1], tau_sh[lq]);

    // pass 2: pruned walk over all other chunks
    for (int c = s; c < NCH; c += NSPL) {
        if (c >= h0 && c <= h1) continue;
        float4 lo = g_chlo[b][c];
        float4 hi = g_chhi[b][c];
        float dx = fmaxf(fmaxf(lo.x - qx, qx - hi.x), 0.f);
        float dy = fmaxf(fmaxf(lo.y - qy, qy - hi.y), 0.f);
        float dz = fmaxf(fmaxf(lo.z - qz, qz - hi.z), 0.f);
        float d2box = fmaf(dx, dx, fmaf(dy, dy, dz * dz));
        float thr = fmaf(2.0f, tau, qr2) * 1.0002f;
        if (__any_sync(FULL, d2box < thr)) SCAN_CHUNK(c);
    }
    COMPACT();
#undef SCAN_CHUNK
#undef COMPACT

    __syncthreads();   // reuse raw for the 4-way merge
    float* md = (float*)raw;                         // 80*32*4 = 10240 B
    int*   mi = (int*)(raw + NSPL * KNN * 32 * 4);   // 10240 B
#pragma unroll
    for (int k = 0; k < KNN; k++) {
        md[(s * KNN + k) * 32 + lq] = bd[k];
        mi[(s * KNN + k) * 32 + lq] = bi[k];
    }
    __syncthreads();

    if (tid < 32) {
        float fd[KNN]; int fi[KNN];
#pragma unroll
        for (int k = 0; k < KNN; k++) { fd[k] = 1e30f; fi[k] = -1; }
        for (int i = 0; i < NSPL * KNN; i++) {
            float d = md[i * 32 + tid];
            int  id = mi[i * 32 + tid];
            if (d < fd[KNN - 1]) {
#pragma unroll
                for (int k = KNN - 1; k > 0; --k) {
                    if (fd[k] > d) {
                        bool sh = fd[k - 1] > d;
                        fd[k] = sh ? fd[k - 1] : d;
                        fi[k] = sh ? fi[k - 1] : id;
                    }
                }
                if (fd[0] > d) { fd[0] = d; fi[0] = id; }
            }
        }
        const int* ids = g_ids + (size_t)b * NPTS;
        int myslot = sbase + tid;
        int* o = g_knn + ((size_t)b * NPTS + ids[myslot]) * KNN;
#pragma unroll
        for (int k = 0; k < KNN; k++) o[k] = ids[fi[k]];
    }
}

// ---------------- main: edge MLP + softmax + aggregation + node MLP ----------------
__global__ __launch_bounds__(256) void main_kernel(
    const float* __restrict__ z,
    const float* __restrict__ We1, const float* __restrict__ We2,
    const float* __restrict__ be2,
    const float* __restrict__ Wn1, const float* __restrict__ Wn2,
    const float* __restrict__ bn2,
    const float* __restrict__ alpha, const float* __restrict__ beta,
    float* __restrict__ out)
{
    __shared__ float4 part[8][KNN][17];

    const unsigned FULL = 0xffffffffu;
    const int wlocal = threadIdx.x >> 5;
    const int warp = (blockIdx.x * blockDim.x + threadIdx.x) >> 5;
    const int lane = threadIdx.x & 31;
    const int b = warp >> 13;
    const int n = warp & (NPTS - 1);

    const float* zb = z + (size_t)b * NPTS * 7;
    const float* zt = zb + (size_t)n * 7;
    const float ptx = zt[0], pty = zt[1], ptz = zt[2];
    const float vtx = zt[3], vty = zt[4], vtz = zt[5];
    const float mt  = zt[6];

    float relx = 0.f, rely = 0.f, relz = 0.f;
    float vsx = 0.f, vsy = 0.f, vsz = 0.f;
    float msrc = 0.f, r2 = 0.f, dvv = 0.f, dvr = 0.f, dtr = 0.f;
    if (lane < KNN) {
        int src = g_knn[(size_t)warp * KNN + lane];
        const float* zs = zb + (size_t)src * 7;
        float sx = zs[0], sy = zs[1], sz = zs[2];
        vsx = zs[3]; vsy = zs[4]; vsz = zs[5]; msrc = zs[6];
        relx = sx - ptx; rely = sy - pty; relz = sz - ptz;
        r2  = relx * relx + rely * rely + relz * relz;
        dvv = vsx * vtx + vsy * vty + vsz * vtz;
        dvr = vsx * relx + vsy * rely + vsz * relz;
        dtr = vtx * relx + vty * rely + vtz * relz;
    }

    float s1[4], s2[4], w72[4], w73[4], w74[4], w75[4], b1[4];
    float4 we2[4];
#pragma unroll
    for (int qq = 0; qq < 4; qq++) {
        int j = lane + 32 * qq;
        s1[qq]  = g_S1[j];
        s2[qq]  = g_S2[j];
        w72[qq] = We1[72 * 128 + j];
        w73[qq] = We1[73 * 128 + j];
        w74[qq] = We1[74 * 128 + j];
        w75[qq] = We1[75 * 128 + j];
        b1[qq]  = g_base1[b][j];
        we2[qq] = ((const float4*)We2)[j];
    }

#pragma unroll
    for (int e = 0; e < KNN; e++) {
        float em   = __shfl_sync(FULL, msrc, e);
        float er2  = __shfl_sync(FULL, r2,   e);
        float edvv = __shfl_sync(FULL, dvv,  e);
        float edvr = __shfl_sync(FULL, dvr,  e);
        float edtr = __shfl_sync(FULL, dtr,  e);
        float p0 = 0.f, p1 = 0.f, p2 = 0.f, p3 = 0.f;
#pragma unroll
        for (int qq = 0; qq < 4; qq++) {
            float h = b1[qq];
            h = fmaf(em,   s1[qq],  h);
            h = fmaf(mt,   s2[qq],  h);
            h = fmaf(er2,  w72[qq], h);
            h = fmaf(edvv, w73[qq], h);
            h = fmaf(edvr, w74[qq], h);
            h = fmaf(edtr, w75[qq], h);
            float g = gelu_fast(h);
            p0 = fmaf(g, we2[qq].x, p0);
            p1 = fmaf(g, we2[qq].y, p1);
            p2 = fmaf(g, we2[qq].z, p2);
            p3 = fmaf(g, we2[qq].w, p3);
        }
        p0 += __shfl_xor_sync(FULL, p0, 16);
        p1 += __shfl_xor_sync(FULL, p1, 16);
        p2 += __shfl_xor_sync(FULL, p2, 16);
        p3 += __shfl_xor_sync(FULL, p3, 16);
        if (lane < 16) part[wlocal][e][lane] = make_float4(p0, p1, p2, p3);
    }
    __syncwarp();

    float elog = -1e30f, esmsg = 0.f, ecrel = 0.f, ecvel = 0.f;
    if (lane < KNN) {
        float4 acc = part[wlocal][lane][0];
#pragma unroll
        for (int i = 1; i < 16; i++) {
            float4 p = part[wlocal][lane][i];
            acc.x += p.x; acc.y += p.y; acc.z += p.z; acc.w += p.w;
        }
        elog  = acc.x + be2[0];
        esmsg = acc.y + be2[1];
        ecrel = acc.z + be2[2];
        ecvel = acc.w + be2[3];
    }

    float lg = (lane < KNN) ? elog : -1e30f;
    float mx = lg;
#pragma unroll
    for (int off = 16; off > 0; off >>= 1)
        mx = fmaxf(mx, __shfl_xor_sync(FULL, mx, off));
    float a = (lane < KNN) ? __expf(lg - mx) : 0.f;
    float den = a;
#pragma unroll
    for (int off = 16; off > 0; off >>= 1)
        den += __shfl_xor_sync(FULL, den, off);
    float w = a / den;

    float vmx = w * (ecrel * relx + ecvel * vsx);
    float vmy = w * (ecrel * rely + ecvel * vsy);
    float vmz = w * (ecrel * relz + ecvel * vsz);
    float sg  = w * esmsg;
#pragma unroll
    for (int off = 16; off > 0; off >>= 1) {
        vmx += __shfl_xor_sync(FULL, vmx, off);
        vmy += __shfl_xor_sync(FULL, vmy, off);
        vmz += __shfl_xor_sync(FULL, vmz, off);
        sg  += __shfl_xor_sync(FULL, sg,  off);
    }

    float acc2 = 0.f;
#pragma unroll
    for (int qq = 0; qq < 2; qq++) {
        int j = lane + 32 * qq;
        float h = g_baseN[b][j];
        h = fmaf(mt, g_SN[j], h);
        h = fmaf(sg, Wn1[36 * 64 + j], h);
        acc2 = fmaf(gelu_fast(h), Wn2[j], acc2);
    }
#pragma unroll
    for (int off = 16; off > 0; off >>= 1)
        acc2 += __shfl_xor_sync(FULL, acc2, off);

    if (lane == 0) {
        float sout = acc2 + bn2[0];
        float al = alpha[0], be = beta[0];
        float* o = out + (size_t)warp * 7;
        o[0] = ptx + (ptx + al * vmx);
        o[1] = pty + (pty + al * vmy);
        o[2] = ptz + (ptz + al * vmz);
        o[3] = vtx + be * vmx;
        o[4] = vty + be * vmy;
        o[5] = vtz + be * vmz;
        o[6] = mt + sout;
    }
}

// ---------------- launch ----------------
extern "C" void kernel_launch(void* const* d_in, const int* in_sizes, int n_in,
                              void* d_out, int out_size)
{
    const float* z    = (const float*)d_in[0];
    const float* t    = (const float*)d_in[1];
    const float* cond = (const float*)d_in[2];
    const float* Wc1 = (const float*)d_in[4];
    const float* bc1 = (const float*)d_in[5];
    const float* Wc2 = (const float*)d_in[6];
    const float* bc2 = (const float*)d_in[7];
    const float* Wc3 = (const float*)d_in[8];
    const float* bc3 = (const float*)d_in[9];
    const float* We1 = (const float*)d_in[10];
    const float* be1 = (const float*)d_in[11];
    const float* We2 = (const float*)d_in[12];
    const float* be2 = (const float*)d_in[13];
    const float* Wn1 = (const float*)d_in[14];
    const float* bn1 = (const float*)d_in[15];
    const float* Wn2 = (const float*)d_in[16];
    const float* bn2 = (const float*)d_in[17];
    const float* alpha = (const float*)d_in[18];
    const float* beta  = (const float*)d_in[19];
    float* out = (float*)d_out;

    build_kernel<<<NB + 1, 1024>>>(z, t, cond, Wc1, bc1, Wc2, bc2,
                                   Wc3, bc3, We1, be1, Wn1, bn1);

    dim3 qg(NPTS / 32, NB);
    knn_query_kernel<<<qg, KTHR>>>();

    int total_warps = NB * NPTS;
    int blocks = total_warps / 8;
    main_kernel<<<blocks, 256>>>(z, We1, We2, be2, Wn1, Wn2, bn2,
                                 alpha, beta, out);
}